// round 11
// baseline (speedup 1.0000x reference)
#include <cuda_runtime.h>
#include <cuda_fp16.h>

// Problem constants
#define SS 4096
#define HH 1024
#define G4 4096   // 4*H

#define NCTA_DIR 74
#define UPC 14            // hidden units per CTA (74*14 = 1036 >= 1024)
#define REC_THREADS 448   // 14 warps, one unit per warp

// Persistent device scratch (allocation-free rule: __device__ globals)
__device__ float  g_xp[2][SS][G4];      // x_proj per direction, 128 MB
__device__ float  g_h[2][2][HH];        // double-buffered fp32 hidden state
__device__ unsigned g_flag[2][8][128];  // per-CTA ready flags, 8-deep ring
__device__ unsigned g_count[2];         // init/exit barrier counters
__device__ unsigned g_phase[2];         // init/exit barrier phases

// ---------------------------------------------------------------------------
// GEMM: x_proj[dir][s][r] = sum_k inputs[s][k] * W[r][1024+k] + b[r]
// (unchanged, validated)
// ---------------------------------------------------------------------------
__global__ void __launch_bounds__(256, 2) xproj_kernel(
    const float* __restrict__ inp,
    const float* __restrict__ W0, const float* __restrict__ b0,
    const float* __restrict__ W1, const float* __restrict__ b1)
{
    const int dir = blockIdx.z;
    const float* __restrict__ W    = dir ? W1 : W0;
    const float* __restrict__ bias = dir ? b1 : b0;
    float* __restrict__ out = &g_xp[dir][0][0];

    const int bm = blockIdx.y, bn = blockIdx.x;
    const int tid = threadIdx.x;
    const int tx = tid & 15, ty = tid >> 4;

    __shared__ float As[2][8][132];
    __shared__ float Bs[2][8][132];

    const int lr = tid >> 1;         // 0..127
    const int lk = (tid & 1) << 2;   // 0 or 4

    const float* Ap = inp + (size_t)(bm * 128 + lr) * 1024 + lk;
    const float* Bp = W   + (size_t)(bn * 128 + lr) * 2048 + 1024 + lk;

    float4 av = *(const float4*)Ap;
    float4 bv = *(const float4*)Bp;
    As[0][lk + 0][lr] = av.x; As[0][lk + 1][lr] = av.y;
    As[0][lk + 2][lr] = av.z; As[0][lk + 3][lr] = av.w;
    Bs[0][lk + 0][lr] = bv.x; Bs[0][lk + 1][lr] = bv.y;
    Bs[0][lk + 2][lr] = bv.z; Bs[0][lk + 3][lr] = bv.w;
    __syncthreads();

    float acc[8][8];
#pragma unroll
    for (int i = 0; i < 8; i++)
#pragma unroll
        for (int j = 0; j < 8; j++) acc[i][j] = 0.f;

    for (int kt = 0; kt < 128; kt++) {
        const int cur = kt & 1;
        if (kt < 127) {
            av = *(const float4*)(Ap + (kt + 1) * 8);
            bv = *(const float4*)(Bp + (kt + 1) * 8);
        }
#pragma unroll
        for (int k = 0; k < 8; k++) {
            float ar[8], bc[8];
            *(float4*)&ar[0] = *(const float4*)&As[cur][k][ty * 4];
            *(float4*)&ar[4] = *(const float4*)&As[cur][k][64 + ty * 4];
            *(float4*)&bc[0] = *(const float4*)&Bs[cur][k][tx * 4];
            *(float4*)&bc[4] = *(const float4*)&Bs[cur][k][64 + tx * 4];
#pragma unroll
            for (int i = 0; i < 8; i++)
#pragma unroll
                for (int j = 0; j < 8; j++)
                    acc[i][j] += ar[i] * bc[j];
        }
        if (kt < 127) {
            const int nxt = cur ^ 1;
            As[nxt][lk + 0][lr] = av.x; As[nxt][lk + 1][lr] = av.y;
            As[nxt][lk + 2][lr] = av.z; As[nxt][lk + 3][lr] = av.w;
            Bs[nxt][lk + 0][lr] = bv.x; Bs[nxt][lk + 1][lr] = bv.y;
            Bs[nxt][lk + 2][lr] = bv.z; Bs[nxt][lk + 3][lr] = bv.w;
        }
        __syncthreads();
    }

    const float4 bias0 = *(const float4*)&bias[bn * 128 + tx * 4];
    const float4 bias1 = *(const float4*)&bias[bn * 128 + 64 + tx * 4];
#pragma unroll
    for (int i = 0; i < 8; i++) {
        const int gr = bm * 128 + ((i < 4) ? (ty * 4 + i) : (64 + ty * 4 + i - 4));
        float4 o0, o1;
        o0.x = acc[i][0] + bias0.x; o0.y = acc[i][1] + bias0.y;
        o0.z = acc[i][2] + bias0.z; o0.w = acc[i][3] + bias0.w;
        o1.x = acc[i][4] + bias1.x; o1.y = acc[i][5] + bias1.y;
        o1.z = acc[i][6] + bias1.z; o1.w = acc[i][7] + bias1.w;
        *(float4*)&out[(size_t)gr * 4096 + bn * 128 + tx * 4]      = o0;
        *(float4*)&out[(size_t)gr * 4096 + bn * 128 + 64 + tx * 4] = o1;
    }
}

// ---------------------------------------------------------------------------
// Proven two-phase grid barrier (R9/R10 scoped-atomics version). Used only
// twice per launch (init + exit) -> even flip count restores phase parity.
// ---------------------------------------------------------------------------
__device__ __forceinline__ void gbar(int dir, unsigned &lp)
{
    __syncthreads();
    if (threadIdx.x == 0) {
        const unsigned np = lp ^ 1u;
        unsigned old;
        asm volatile("atom.acq_rel.gpu.global.add.u32 %0, [%1], %2;"
                     : "=r"(old) : "l"(&g_count[dir]), "r"(1u) : "memory");
        if (old == (unsigned)(NCTA_DIR - 1)) {
            asm volatile("st.relaxed.gpu.global.u32 [%0], %1;"
                         :: "l"(&g_count[dir]), "r"(0u) : "memory");
            asm volatile("st.release.gpu.global.u32 [%0], %1;"
                         :: "l"(&g_phase[dir]), "r"(np) : "memory");
        } else {
            unsigned v;
            do {
                asm volatile("ld.acquire.gpu.global.u32 %0, [%1];"
                             : "=r"(v) : "l"(&g_phase[dir]) : "memory");
            } while (v != np);
        }
    }
    __syncthreads();
    lp ^= 1u;
}

__device__ __forceinline__ unsigned ld_acquire(const unsigned* p) {
    unsigned v;
    asm volatile("ld.acquire.gpu.global.u32 %0, [%1];"
                 : "=r"(v) : "l"(p) : "memory");
    return v;
}
__device__ __forceinline__ void st_release(unsigned* p, unsigned v) {
    asm volatile("st.release.gpu.global.u32 [%0], %1;"
                 :: "l"(p), "r"(v) : "memory");
}

__device__ __forceinline__ float fsigmoid(float x) {
    return 1.f / (1.f + __expf(-x));
}
__device__ __forceinline__ float ftanh(float x) {
    return 2.f / (1.f + __expf(-2.f * x)) - 1.f;
}

// ---------------------------------------------------------------------------
// Persistent recurrence kernel. 148 CTAs (one wave), 74 per direction.
// Each warp owns one hidden unit; 4 Wh gate rows as fp16 in registers.
// h exchanged via L2 fp32, staged into SMEM per step.
// Sync: decentralized per-producer-CTA ready flags (release/acquire),
// 8-deep step-indexed ring. Producer skew provably <= 2 steps, so ring-8
// and double-buffered h are safe. Replay-safe: each CTA zeroes its own
// flags before the init gbar; gbar used exactly twice (parity restored).
// ---------------------------------------------------------------------------
__global__ void __launch_bounds__(REC_THREADS, 1) lstm_rec_kernel(
    const float* __restrict__ W0, const float* __restrict__ W1,
    float* __restrict__ out)
{
    __shared__ float4 sh4[256];   // staged h (1024 floats)

    const int dir  = (blockIdx.x >= NCTA_DIR) ? 1 : 0;
    const int cta  = blockIdx.x - dir * NCTA_DIR;
    const int u0   = cta * UPC;
    const int nu   = (HH - u0 < UPC) ? (HH - u0) : UPC;
    const int tid  = threadIdx.x;
    const int w    = tid >> 5;
    const int lane = tid & 31;
    const float* __restrict__ Wsrc = dir ? W1 : W0;

    const int active = (w < nu);
    const int u = u0 + w;
    const int uu = active ? u : u0;

    // Flag sources for this stager's float4 chunk (units 4*tid .. 4*tid+3)
    const int ca = (4 * tid) / UPC;        // valid for tid < 256
    const int cb = (4 * tid + 3) / UPC;
    const unsigned* fa = &g_flag[dir][0][ca < 128 ? ca : 0];
    const unsigned* fb = &g_flag[dir][0][cb < 128 ? cb : 0];
    const bool dual = (cb != ca);

    // Register-resident fp16 weights, interleaved layout:
    // lane owns float4-chunks f = j*32 + lane (cols 4f..4f+3), j = 0..7.
    __half2 wr[4][16];
#pragma unroll
    for (int r = 0; r < 4; r++) {
        const float* src = Wsrc + (size_t)((r << 10) + uu) * 2048;
#pragma unroll
        for (int j = 0; j < 8; j++) {
            const float4 a = *(const float4*)(src + 4 * (j * 32 + lane));
            wr[r][2 * j]     = __floats2half2_rn(a.x, a.y);
            wr[r][2 * j + 1] = __floats2half2_rn(a.z, a.w);
        }
    }

    // Init: zero my flag ring, set slot0 = 1 (h@0 ready), zero h@0.
    if (tid < 8) g_flag[dir][tid][cta] = 0u;
    if (tid == 0) g_flag[dir][0][cta] = 1u;   // same thread as slot0 zero: ordered
    if (active && lane == 0) g_h[dir][0][u] = 0.f;

    unsigned lp = 0;
    gbar(dir, lp);   // barrier #1: flags + h0 globally visible

    float c = 0.f, hlast = 0.f;

    // x_proj register double-buffer (prefetch one step ahead)
    float x0n = 0.f, x1n = 0.f, x2n = 0.f, x3n = 0.f;
    if (active && lane == 0) {
        const int te0 = dir ? (SS - 1) : 0;
        const float* xp = &g_xp[dir][te0][0];
        x0n = __ldg(xp + u);
        x1n = __ldg(xp + HH + u);
        x2n = __ldg(xp + 2 * HH + u);
        x3n = __ldg(xp + 3 * HH + u);
    }

    for (int t = 0; t < SS; t++) {
        const int te  = dir ? (SS - 1 - t) : t;
        const int pin = t & 1;

        // rotate x buffer and issue next prefetch early (overlaps the spin)
        const float x0 = x0n, x1 = x1n, x2 = x2n, x3 = x3n;
        if (t + 1 < SS && active && lane == 0) {
            const int te1 = dir ? (SS - 2 - t) : (t + 1);
            const float* xp = &g_xp[dir][te1][0];
            x0n = __ldg(xp + u);
            x1n = __ldg(xp + HH + u);
            x2n = __ldg(xp + 2 * HH + u);
            x3n = __ldg(xp + 3 * HH + u);
        }

        // ---- stage h@t: wait on source-CTA flags, then pull float4 ----
        if (tid < 256) {
            const unsigned expect = (unsigned)(t + 1);
            const int slotoff = (t & 7) * 128;
            while (ld_acquire(fa + slotoff) != expect) {}
            if (dual) { while (ld_acquire(fb + slotoff) != expect) {} }
            sh4[tid] = __ldcg((const float4*)&g_h[dir][pin][0] + tid);
        }
        __syncthreads();   // staged h visible to all warps

        if (active) {
            float a0 = 0.f, a1 = 0.f, a2 = 0.f, a3 = 0.f;
#pragma unroll
            for (int j = 0; j < 8; j++) {
                const float4 hv = sh4[j * 32 + lane];  // conflict-free LDS.128
#pragma unroll
                for (int r = 0; r < 4; r++) {
                    const float2 p0 = __half22float2(wr[r][2 * j]);
                    const float2 p1 = __half22float2(wr[r][2 * j + 1]);
                    const float s = fmaf(p0.x, hv.x, fmaf(p0.y, hv.y,
                                    fmaf(p1.x, hv.z, p1.y * hv.w)));
                    if (r == 0) a0 += s;
                    else if (r == 1) a1 += s;
                    else if (r == 2) a2 += s;
                    else a3 += s;
                }
            }
#pragma unroll
            for (int off = 16; off; off >>= 1) {
                a0 += __shfl_xor_sync(0xffffffffu, a0, off);
                a1 += __shfl_xor_sync(0xffffffffu, a1, off);
                a2 += __shfl_xor_sync(0xffffffffu, a2, off);
                a3 += __shfl_xor_sync(0xffffffffu, a3, off);
            }
            if (lane == 0) {
                const float fg = fsigmoid(a0 + x0);
                const float ig = fsigmoid(a1 + x1);
                const float gg = ftanh(a2 + x2);
                const float og = fsigmoid(a3 + x3);
                c = fg * c + ig * gg;
                const float hvv = og * ftanh(c);
                hlast = hvv;
                g_h[dir][pin ^ 1][u] = hvv;
                out[(size_t)te * 2048 + dir * 1024 + u] = hvv;
            }
        }

        // ---- publish h@{t+1}: block-local fence, then per-CTA release ----
        __syncthreads();   // all lane0 h-stores done (also protects sh4 reuse)
        if (tid == 0 && t + 1 < SS) {
            st_release(&g_flag[dir][(t + 1) & 7][cta], (unsigned)(t + 2));
        }
    }

    if (active && lane == 0)
        out[(size_t)SS * 2048 + dir * 1024 + u] = hlast;

    gbar(dir, lp);       // barrier #2: even count -> phase parity restored
}

// ---------------------------------------------------------------------------
// kernel_launch: GEMM (both directions) then persistent recurrence.
// ---------------------------------------------------------------------------
extern "C" void kernel_launch(void* const* d_in, const int* in_sizes, int n_in,
                              void* d_out, int out_size)
{
    const float* inp = (const float*)d_in[0];
    const float* Wf  = (const float*)d_in[1];
    const float* bf  = (const float*)d_in[2];
    const float* Wb  = (const float*)d_in[3];
    const float* bb  = (const float*)d_in[4];
    float* out = (float*)d_out;

    (void)in_sizes; (void)n_in; (void)out_size;

    dim3 ggrid(32, 32, 2);
    xproj_kernel<<<ggrid, 256>>>(inp, Wf, bf, Wb, bb);
    lstm_rec_kernel<<<2 * NCTA_DIR, REC_THREADS>>>(Wf, Wb, out);
}

// round 12
// speedup vs baseline: 1.9366x; 1.9366x over previous
#include <cuda_runtime.h>
#include <cuda_fp16.h>

// Problem constants
#define SS 4096
#define HH 1024
#define G4 4096   // 4*H

#define NCTA_DIR 74
#define UPC 14            // hidden units per CTA (74*14 = 1036 >= 1024)
#define REC_THREADS 448   // 14 warps, one unit per warp

// Persistent device scratch (allocation-free rule: __device__ globals)
__device__ float  g_xp[2][SS][G4];      // x_proj per direction, 128 MB
__device__ float  g_h[2][2][HH];        // double-buffered fp32 hidden state
__device__ unsigned g_mcount[2][32];    // monotonic step counters (padded lines)
__device__ unsigned g_count[2];         // exit-barrier counters (self-resetting)
__device__ unsigned g_phase[2];         // exit-barrier phases (parity-restored)

// ---------------------------------------------------------------------------
// GEMM: x_proj[dir][s][r] = sum_k inputs[s][k] * W[r][1024+k] + b[r]
// (unchanged, validated)
// ---------------------------------------------------------------------------
__global__ void __launch_bounds__(256, 2) xproj_kernel(
    const float* __restrict__ inp,
    const float* __restrict__ W0, const float* __restrict__ b0,
    const float* __restrict__ W1, const float* __restrict__ b1)
{
    const int dir = blockIdx.z;
    const float* __restrict__ W    = dir ? W1 : W0;
    const float* __restrict__ bias = dir ? b1 : b0;
    float* __restrict__ out = &g_xp[dir][0][0];

    const int bm = blockIdx.y, bn = blockIdx.x;
    const int tid = threadIdx.x;
    const int tx = tid & 15, ty = tid >> 4;

    __shared__ float As[2][8][132];
    __shared__ float Bs[2][8][132];

    const int lr = tid >> 1;         // 0..127
    const int lk = (tid & 1) << 2;   // 0 or 4

    const float* Ap = inp + (size_t)(bm * 128 + lr) * 1024 + lk;
    const float* Bp = W   + (size_t)(bn * 128 + lr) * 2048 + 1024 + lk;

    float4 av = *(const float4*)Ap;
    float4 bv = *(const float4*)Bp;
    As[0][lk + 0][lr] = av.x; As[0][lk + 1][lr] = av.y;
    As[0][lk + 2][lr] = av.z; As[0][lk + 3][lr] = av.w;
    Bs[0][lk + 0][lr] = bv.x; Bs[0][lk + 1][lr] = bv.y;
    Bs[0][lk + 2][lr] = bv.z; Bs[0][lk + 3][lr] = bv.w;
    __syncthreads();

    float acc[8][8];
#pragma unroll
    for (int i = 0; i < 8; i++)
#pragma unroll
        for (int j = 0; j < 8; j++) acc[i][j] = 0.f;

    for (int kt = 0; kt < 128; kt++) {
        const int cur = kt & 1;
        if (kt < 127) {
            av = *(const float4*)(Ap + (kt + 1) * 8);
            bv = *(const float4*)(Bp + (kt + 1) * 8);
        }
#pragma unroll
        for (int k = 0; k < 8; k++) {
            float ar[8], bc[8];
            *(float4*)&ar[0] = *(const float4*)&As[cur][k][ty * 4];
            *(float4*)&ar[4] = *(const float4*)&As[cur][k][64 + ty * 4];
            *(float4*)&bc[0] = *(const float4*)&Bs[cur][k][tx * 4];
            *(float4*)&bc[4] = *(const float4*)&Bs[cur][k][64 + tx * 4];
#pragma unroll
            for (int i = 0; i < 8; i++)
#pragma unroll
                for (int j = 0; j < 8; j++)
                    acc[i][j] += ar[i] * bc[j];
        }
        if (kt < 127) {
            const int nxt = cur ^ 1;
            As[nxt][lk + 0][lr] = av.x; As[nxt][lk + 1][lr] = av.y;
            As[nxt][lk + 2][lr] = av.z; As[nxt][lk + 3][lr] = av.w;
            Bs[nxt][lk + 0][lr] = bv.x; Bs[nxt][lk + 1][lr] = bv.y;
            Bs[nxt][lk + 2][lr] = bv.z; Bs[nxt][lk + 3][lr] = bv.w;
        }
        __syncthreads();
    }

    const float4 bias0 = *(const float4*)&bias[bn * 128 + tx * 4];
    const float4 bias1 = *(const float4*)&bias[bn * 128 + 64 + tx * 4];
#pragma unroll
    for (int i = 0; i < 8; i++) {
        const int gr = bm * 128 + ((i < 4) ? (ty * 4 + i) : (64 + ty * 4 + i - 4));
        float4 o0, o1;
        o0.x = acc[i][0] + bias0.x; o0.y = acc[i][1] + bias0.y;
        o0.z = acc[i][2] + bias0.z; o0.w = acc[i][3] + bias0.w;
        o1.x = acc[i][4] + bias1.x; o1.y = acc[i][5] + bias1.y;
        o1.z = acc[i][6] + bias1.z; o1.w = acc[i][7] + bias1.w;
        *(float4*)&out[(size_t)gr * 4096 + bn * 128 + tx * 4]      = o0;
        *(float4*)&out[(size_t)gr * 4096 + bn * 128 + 64 + tx * 4] = o1;
    }
}

// ---------------------------------------------------------------------------
// Proven two-phase grid barrier (R9/R10). Used exactly twice per launch
// (exit protocol) -> even flip count restores phase parity for graph replay.
// ---------------------------------------------------------------------------
__device__ __forceinline__ void gbar(int dir, unsigned &lp)
{
    __syncthreads();
    if (threadIdx.x == 0) {
        const unsigned np = lp ^ 1u;
        unsigned old;
        asm volatile("atom.acq_rel.gpu.global.add.u32 %0, [%1], %2;"
                     : "=r"(old) : "l"(&g_count[dir]), "r"(1u) : "memory");
        if (old == (unsigned)(NCTA_DIR - 1)) {
            asm volatile("st.relaxed.gpu.global.u32 [%0], %1;"
                         :: "l"(&g_count[dir]), "r"(0u) : "memory");
            asm volatile("st.release.gpu.global.u32 [%0], %1;"
                         :: "l"(&g_phase[dir]), "r"(np) : "memory");
        } else {
            unsigned v;
            do {
                asm volatile("ld.acquire.gpu.global.u32 %0, [%1];"
                             : "=r"(v) : "l"(&g_phase[dir]) : "memory");
            } while (v != np);
        }
    }
    __syncthreads();
    lp ^= 1u;
}

__device__ __forceinline__ unsigned ld_acquire(const unsigned* p) {
    unsigned v;
    asm volatile("ld.acquire.gpu.global.u32 %0, [%1];"
                 : "=r"(v) : "l"(p) : "memory");
    return v;
}
// Fire-and-forget release arrival: RED (no return) -> pipelined at LTS,
// no per-arrival round trip, no last-arriver serialization.
__device__ __forceinline__ void red_release_add(unsigned* p, unsigned v) {
    asm volatile("red.release.gpu.global.add.u32 [%0], %1;"
                 :: "l"(p), "r"(v) : "memory");
}

__device__ __forceinline__ float fsigmoid(float x) {
    return 1.f / (1.f + __expf(-x));
}
__device__ __forceinline__ float ftanh(float x) {
    return 2.f / (1.f + __expf(-2.f * x)) - 1.f;
}

// ---------------------------------------------------------------------------
// Persistent recurrence kernel. 148 CTAs (one wave), 74 per direction.
// Each warp owns one hidden unit; 4 Wh gate rows as fp16 in registers.
// h exchanged via L2 fp32, staged into SMEM per step.
// Sync: monotonic counter wave. Arrive = red.release.add (fire-and-forget);
// wait = ONE spinner per CTA doing ld.acquire until counter >= 74*(t+1).
// Lockstep invariant: entering step t requires all CTAs finished step t-1,
// hence done reading the h buffer step t overwrites (double buffer safe,
// max skew = 1 compute region — identical guarantee to R10's gbar).
// Replay-safe: counter reset by CTA0-per-dir between two proven gbar calls.
// ---------------------------------------------------------------------------
__global__ void __launch_bounds__(REC_THREADS, 1) lstm_rec_kernel(
    const float* __restrict__ W0, const float* __restrict__ W1,
    float* __restrict__ out)
{
    __shared__ float4 sh4[256];   // staged h (1024 floats)

    const int dir  = (blockIdx.x >= NCTA_DIR) ? 1 : 0;
    const int cta  = blockIdx.x - dir * NCTA_DIR;
    const int u0   = cta * UPC;
    const int nu   = (HH - u0 < UPC) ? (HH - u0) : UPC;
    const int tid  = threadIdx.x;
    const int w    = tid >> 5;
    const int lane = tid & 31;
    const float* __restrict__ Wsrc = dir ? W1 : W0;
    unsigned* const mcnt = &g_mcount[dir][0];

    const int active = (w < nu);
    const int u = u0 + w;
    const int uu = active ? u : u0;

    // Register-resident fp16 weights, interleaved layout:
    // lane owns float4-chunks f = j*32 + lane (cols 4f..4f+3), j = 0..7.
    __half2 wr[4][16];
#pragma unroll
    for (int r = 0; r < 4; r++) {
        const float* src = Wsrc + (size_t)((r << 10) + uu) * 2048;
#pragma unroll
        for (int j = 0; j < 8; j++) {
            const float4 a = *(const float4*)(src + 4 * (j * 32 + lane));
            wr[r][2 * j]     = __floats2half2_rn(a.x, a.y);
            wr[r][2 * j + 1] = __floats2half2_rn(a.z, a.w);
        }
    }

    if (active && lane == 0) g_h[dir][0][u] = 0.f;

    // Initial publish: h@0 ready (arrival #1). Counter was 0 at launch.
    __syncthreads();
    if (tid == 0) red_release_add(mcnt, 1u);

    float c = 0.f, hlast = 0.f;

    // x_proj register double-buffer (prefetch one step ahead)
    float x0n = 0.f, x1n = 0.f, x2n = 0.f, x3n = 0.f;
    if (active && lane == 0) {
        const int te0 = dir ? (SS - 1) : 0;
        const float* xp = &g_xp[dir][te0][0];
        x0n = __ldg(xp + u);
        x1n = __ldg(xp + HH + u);
        x2n = __ldg(xp + 2 * HH + u);
        x3n = __ldg(xp + 3 * HH + u);
    }

    for (int t = 0; t < SS; t++) {
        const int te  = dir ? (SS - 1 - t) : t;
        const int pin = t & 1;

        // rotate x buffer; issue next prefetch early (overlaps the wait)
        const float x0 = x0n, x1 = x1n, x2 = x2n, x3 = x3n;
        if (t + 1 < SS && active && lane == 0) {
            const int te1 = dir ? (SS - 2 - t) : (t + 1);
            const float* xp = &g_xp[dir][te1][0];
            x0n = __ldg(xp + u);
            x1n = __ldg(xp + HH + u);
            x2n = __ldg(xp + 2 * HH + u);
            x3n = __ldg(xp + 3 * HH + u);
        }

        // ---- wait: all CTAs published h@t (single spinner per CTA) ----
        if (tid == 0) {
            const unsigned tgt = (unsigned)(t + 1) * NCTA_DIR;
            while (ld_acquire(mcnt) < tgt) {}
        }
        __syncthreads();   // propagate acquired view to the whole block

        // ---- stage h@t into SMEM (coherent L2 loads) ----
        if (tid < 256) {
            sh4[tid] = __ldcg((const float4*)&g_h[dir][pin][0] + tid);
        }
        __syncthreads();   // staged h visible to all warps

        if (active) {
            float a0 = 0.f, a1 = 0.f, a2 = 0.f, a3 = 0.f;
#pragma unroll
            for (int j = 0; j < 8; j++) {
                const float4 hv = sh4[j * 32 + lane];  // conflict-free LDS.128
#pragma unroll
                for (int r = 0; r < 4; r++) {
                    const float2 p0 = __half22float2(wr[r][2 * j]);
                    const float2 p1 = __half22float2(wr[r][2 * j + 1]);
                    const float s = fmaf(p0.x, hv.x, fmaf(p0.y, hv.y,
                                    fmaf(p1.x, hv.z, p1.y * hv.w)));
                    if (r == 0) a0 += s;
                    else if (r == 1) a1 += s;
                    else if (r == 2) a2 += s;
                    else a3 += s;
                }
            }
#pragma unroll
            for (int off = 16; off; off >>= 1) {
                a0 += __shfl_xor_sync(0xffffffffu, a0, off);
                a1 += __shfl_xor_sync(0xffffffffu, a1, off);
                a2 += __shfl_xor_sync(0xffffffffu, a2, off);
                a3 += __shfl_xor_sync(0xffffffffu, a3, off);
            }
            if (lane == 0) {
                const float fg = fsigmoid(a0 + x0);
                const float ig = fsigmoid(a1 + x1);
                const float gg = ftanh(a2 + x2);
                const float og = fsigmoid(a3 + x3);
                c = fg * c + ig * gg;
                const float hvv = og * ftanh(c);
                hlast = hvv;
                g_h[dir][pin ^ 1][u] = hvv;
                out[(size_t)te * 2048 + dir * 1024 + u] = hvv;
            }
        }

        // ---- publish h@{t+1} (arrival; also protects sh4 reuse) ----
        __syncthreads();
        if (tid == 0) red_release_add(mcnt, 1u);
    }

    if (active && lane == 0)
        out[(size_t)SS * 2048 + dir * 1024 + u] = hlast;

    // ---- exit protocol: reset monotonic counter for next graph replay ----
    unsigned lp = 0;
    gbar(dir, lp);               // all CTAs of this dir done (incl. final REDs
                                 // ordered before the acq_rel arrive chain)
    if (cta == 0 && tid == 0) {
        asm volatile("st.relaxed.gpu.global.u32 [%0], %1;"
                     :: "l"(mcnt), "r"(0u) : "memory");
    }
    gbar(dir, lp);               // reset visible before exit; parity restored
}

// ---------------------------------------------------------------------------
// kernel_launch: GEMM (both directions) then persistent recurrence.
// ---------------------------------------------------------------------------
extern "C" void kernel_launch(void* const* d_in, const int* in_sizes, int n_in,
                              void* d_out, int out_size)
{
    const float* inp = (const float*)d_in[0];
    const float* Wf  = (const float*)d_in[1];
    const float* bf  = (const float*)d_in[2];
    const float* Wb  = (const float*)d_in[3];
    const float* bb  = (const float*)d_in[4];
    float* out = (float*)d_out;

    (void)in_sizes; (void)n_in; (void)out_size;

    dim3 ggrid(32, 32, 2);
    xproj_kernel<<<ggrid, 256>>>(inp, Wf, bf, Wb, bb);
    lstm_rec_kernel<<<2 * NCTA_DIR, REC_THREADS>>>(Wf, Wb, out);
}